// round 9
// baseline (speedup 1.0000x reference)
#include <cuda_runtime.h>
#include <cuda_bf16.h>
#include <cstdint>
#include <cstddef>

// Problem shape (fixed): B=4, S=2048, H=2048, I=4096
constexpr int H_DIM = 2048;
constexpr int I_DIM = 4096;
constexpr int TOK   = 8192;

// ---------------------------------------------------------------------------
// Scratch (device globals; no allocation allowed).
// NOTE: int8_t (signed char) everywhere — plain `char` is unsigned on the
// aarch64 GPU host, and float->unsigned char saturates negatives to 0.
// ---------------------------------------------------------------------------
__device__ float  g_wscale[2];
__device__ double g_part[1024];
__device__ int8_t g_wq_up[(size_t)I_DIM * H_DIM];   // ternary weights, s8
__device__ int8_t g_wq_dn[(size_t)H_DIM * I_DIM];
__device__ int8_t g_xq1[(size_t)TOK * H_DIM];       // quantized acts, s8
__device__ int8_t g_xq2[(size_t)TOK * I_DIM];
__device__ float g_h[(size_t)TOK * I_DIM];          // relu^2 intermediate, fp32
__device__ float g_sx1[TOK];
__device__ float g_sx2[TOK];

// ---------------------------------------------------------------------------
// PTX helpers (arch-neutral: cp.async / ldmatrix / IMMA)
// ---------------------------------------------------------------------------
__device__ __forceinline__ uint32_t smem_u32(const void* p) {
    uint32_t a;
    asm("{ .reg .u64 t; cvta.to.shared.u64 t, %1; cvt.u32.u64 %0, t; }" : "=r"(a) : "l"(p));
    return a;
}
__device__ __forceinline__ void cp_async16(uint32_t s, const void* g) {
    asm volatile("cp.async.cg.shared.global [%0], [%1], 16;" :: "r"(s), "l"(g));
}
__device__ __forceinline__ void cp_commit() {
    asm volatile("cp.async.commit_group;" ::: "memory");
}
__device__ __forceinline__ void cp_wait1() {
    asm volatile("cp.async.wait_group 1;" ::: "memory");
}
__device__ __forceinline__ void ldsm4(uint32_t* r, uint32_t addr) {
    asm volatile("ldmatrix.sync.aligned.m8n8.x4.shared.b16 {%0,%1,%2,%3}, [%4];"
                 : "=r"(r[0]), "=r"(r[1]), "=r"(r[2]), "=r"(r[3]) : "r"(addr));
}
__device__ __forceinline__ void mma_s8(int* d, const uint32_t* a, const uint32_t* b) {
    asm volatile(
        "mma.sync.aligned.m16n8k32.row.col.s32.s8.s8.s32 "
        "{%0,%1,%2,%3}, {%4,%5,%6,%7}, {%8,%9}, {%0,%1,%2,%3};"
        : "+r"(d[0]), "+r"(d[1]), "+r"(d[2]), "+r"(d[3])
        : "r"(a[0]), "r"(a[1]), "r"(a[2]), "r"(a[3]), "r"(b[0]), "r"(b[1]));
}

// ---------------------------------------------------------------------------
// Weight abs-mean (deterministic two-pass) + ternary s8 quantization
// ---------------------------------------------------------------------------
__global__ __launch_bounds__(256) void absmean_partial_kernel(const float* __restrict__ w, int n) {
    __shared__ double sm[256];
    const float4* w4 = (const float4*)w;
    int n4 = n >> 2;
    double acc = 0.0;
    for (int i = blockIdx.x * 256 + threadIdx.x; i < n4; i += 1024 * 256) {
        float4 v = w4[i];
        acc += (double)(fabsf(v.x) + fabsf(v.y)) + (double)(fabsf(v.z) + fabsf(v.w));
    }
    sm[threadIdx.x] = acc;
    __syncthreads();
    for (int s = 128; s > 0; s >>= 1) {
        if (threadIdx.x < s) sm[threadIdx.x] += sm[threadIdx.x + s];
        __syncthreads();
    }
    if (threadIdx.x == 0) g_part[blockIdx.x] = sm[0];
}

__global__ void absmean_final_kernel(int n, int which) {
    __shared__ double sm[256];
    const int t = threadIdx.x;
    sm[t] = g_part[t] + g_part[t + 256] + g_part[t + 512] + g_part[t + 768];
    __syncthreads();
    for (int s = 128; s > 0; s >>= 1) {
        if (t < s) sm[t] += sm[t + s];
        __syncthreads();
    }
    if (t == 0) g_wscale[which] = fmaxf((float)(sm[0] / (double)n), 1e-5f);
}

__global__ __launch_bounds__(256) void quant_w_kernel(const float* __restrict__ w, int n, int which) {
    int8_t* wq = which ? g_wq_dn : g_wq_up;
    const float inv = 1.0f / g_wscale[which];
    const float4* w4 = (const float4*)w;
    int n4 = n >> 2;
    for (int i = blockIdx.x * blockDim.x + threadIdx.x; i < n4; i += gridDim.x * blockDim.x) {
        float4 v = w4[i];
        char4 o;   // char4 members are explicitly signed char
        o.x = (signed char)(int)fminf(fmaxf(rintf(v.x * inv), -1.f), 1.f);
        o.y = (signed char)(int)fminf(fmaxf(rintf(v.y * inv), -1.f), 1.f);
        o.z = (signed char)(int)fminf(fmaxf(rintf(v.z * inv), -1.f), 1.f);
        o.w = (signed char)(int)fminf(fmaxf(rintf(v.w * inv), -1.f), 1.f);
        ((char4*)wq)[i] = o;
    }
}

// ---------------------------------------------------------------------------
// FWHT + per-token absmax quant to s8: regs -> shfl -> smem transpose -> regs.
// Butterfly pairing identical to the reference (order-exact).
// ---------------------------------------------------------------------------
template <int N, int LAYER>
__global__ __launch_bounds__(256) void fwht_quant_kernel(const float* __restrict__ xin) {
    constexpr int E = N / 256;                 // 8 or 16 elems/thread
    __shared__ float buf[N + N / 32];
    __shared__ float red[9];
    const int t = threadIdx.x, lane = t & 31, wid = t >> 5;

    const float* src  = (LAYER == 0) ? xin : g_h;
    int8_t* xq        = (LAYER == 0) ? g_xq1 : g_xq2;
    float* sxp        = (LAYER == 0) ? g_sx1 : g_sx2;
    const float* row  = src + (size_t)blockIdx.x * N;

    float x[E];
#pragma unroll
    for (int q = 0; q < E / 4; q++) {
        float4 v = ((const float4*)row)[t * (E / 4) + q];
        x[q * 4] = v.x; x[q * 4 + 1] = v.y; x[q * 4 + 2] = v.z; x[q * 4 + 3] = v.w;
    }
#pragma unroll
    for (int h = 1; h < E; h <<= 1)
#pragma unroll
        for (int i = 0; i < E; i++)
            if ((i & h) == 0) { float a = x[i], b = x[i + h]; x[i] = a + b; x[i + h] = a - b; }
#pragma unroll
    for (int m = 1; m <= 16; m <<= 1)
#pragma unroll
        for (int i = 0; i < E; i++) {
            float y = __shfl_xor_sync(0xffffffffu, x[i], m);
            x[i] = (lane & m) ? (y - x[i]) : (x[i] + y);
        }
#pragma unroll
    for (int i = 0; i < E; i++) { int e = t * E + i; buf[e + (e >> 5)] = x[i]; }
    __syncthreads();

    const float norm = 1.0f / sqrtf((float)N);
    float y[E];
    float mabs = 0.0f;
#pragma unroll
    for (int k = 0; k < E / 8; k++) {
        float z[8];
#pragma unroll
        for (int j = 0; j < 8; j++) { int e = j * (N / 8) + k * 256 + t; z[j] = buf[e + (e >> 5)]; }
#pragma unroll
        for (int h = 1; h < 8; h <<= 1)
#pragma unroll
            for (int j = 0; j < 8; j++)
                if ((j & h) == 0) { float a = z[j], b = z[j + h]; z[j] = a + b; z[j + h] = a - b; }
#pragma unroll
        for (int j = 0; j < 8; j++) {
            float v = z[j] * norm;
            y[k * 8 + j] = v;
            mabs = fmaxf(mabs, fabsf(v));
        }
    }
#pragma unroll
    for (int m = 16; m > 0; m >>= 1) mabs = fmaxf(mabs, __shfl_xor_sync(0xffffffffu, mabs, m));
    if (lane == 0) red[wid] = mabs;
    __syncthreads();
    if (t == 0) {
        float mm = red[0];
#pragma unroll
        for (int w = 1; w < 8; w++) mm = fmaxf(mm, red[w]);
        red[8] = 127.0f / fmaxf(mm, 1e-5f);
    }
    __syncthreads();
    const float scale = red[8];

    int8_t* dst = xq + (size_t)blockIdx.x * N;
#pragma unroll
    for (int k = 0; k < E / 8; k++)
#pragma unroll
        for (int j = 0; j < 8; j++) {
            float q = fminf(fmaxf(rintf(y[k * 8 + j] * scale), -127.f), 127.f);
            dst[j * (N / 8) + k * 256 + t] = (int8_t)(int)q;   // float->signed int: exact
        }
    if (t == 0) sxp[blockIdx.x] = scale;
}

// ---------------------------------------------------------------------------
// s8 IMMA GEMM: C[M,N] = A[M,K] * B[N,K]^T, exact s32 accumulation.
// BM=BN=128, BK=128 (128B rows, XOR swizzle), 3-stage cp.async pipeline,
// 8 warps (2x4), warp tile 64x32, mma.sync m16n8k32.
// ---------------------------------------------------------------------------
constexpr int GBM = 128, GBN = 128, GBK = 128;
constexpr int STAGE_BYTES = GBM * GBK + GBN * GBK;        // 32768
constexpr int SMEM_GEMM = 3 * STAGE_BYTES;                // 98304

#define SWZ(r, chunk) (((r) * 128) + ((((chunk) ^ ((r) & 7))) << 4))

template <int LAYER>
__global__ __launch_bounds__(256, 2) void gemm_imma_kernel(float* __restrict__ Cout) {
    constexpr int N = LAYER ? H_DIM : I_DIM;
    constexpr int K = LAYER ? I_DIM : H_DIM;
    constexpr int KITERS = K / GBK;

    extern __shared__ char smem[];
    const uint32_t sb = smem_u32(smem);

    const int8_t* A  = LAYER ? g_xq2  : g_xq1;
    const int8_t* Bw = LAYER ? g_wq_dn : g_wq_up;
    float* C         = LAYER ? Cout   : g_h;
    const float* sx  = LAYER ? g_sx2  : g_sx1;

    const int t = threadIdx.x, lane = t & 31, warp = t >> 5;
    const int wm = warp & 1;          // 2 warp rows * 64
    const int wn = warp >> 1;         // 4 warp cols * 32
    const int bm = blockIdx.y, bn = blockIdx.x;

    const int8_t* Ag = A  + (size_t)bm * GBM * K;
    const int8_t* Bg = Bw + (size_t)bn * GBN * K;

    // cp.async thread mapping: chunk = 16B; A: 128 rows x 8 chunks; B same.
    const int lr = t >> 3;            // 0..31 row group
    const int lc = t & 7;             // chunk in row

    auto load_stage = [&](int it) {
        const int s = it % 3;
        const uint32_t As = sb + s * STAGE_BYTES;
        const uint32_t Bs = As + GBM * GBK;
        const int kt = it * GBK;
#pragma unroll
        for (int q = 0; q < 4; q++) {
            int r = lr + q * 32;
            cp_async16(As + SWZ(r, lc), Ag + (size_t)r * K + kt + lc * 16);
        }
#pragma unroll
        for (int q = 0; q < 4; q++) {
            int r = lr + q * 32;
            cp_async16(Bs + SWZ(r, lc), Bg + (size_t)r * K + kt + lc * 16);
        }
        cp_commit();
    };

    int acc[4][4][4];
#pragma unroll
    for (int i = 0; i < 4; i++)
#pragma unroll
        for (int j = 0; j < 4; j++)
#pragma unroll
            for (int e = 0; e < 4; e++) acc[i][j][e] = 0;

    // ldmatrix lane geometry
    const int tIdx = lane >> 3, rowIn = lane & 7;
    int aR[4], bR[2];
#pragma unroll
    for (int i = 0; i < 4; i++) aR[i] = wm * 64 + i * 16 + ((tIdx & 1) << 3) + rowIn;
#pragma unroll
    for (int j2 = 0; j2 < 2; j2++) bR[j2] = wn * 32 + j2 * 16 + ((tIdx >> 1) << 3) + rowIn;
    const int aHi = tIdx >> 1;        // A k-half selector
    const int bHi = tIdx & 1;         // B k-half selector

    load_stage(0);
    load_stage(1);

    for (int it = 0; it < KITERS; ++it) {
        cp_wait1();
        __syncthreads();
        const int s = it % 3;
        const uint32_t As = sb + s * STAGE_BYTES;
        const uint32_t Bs = As + GBM * GBK;

#pragma unroll
        for (int ks = 0; ks < 4; ks++) {
            uint32_t afr[4][4], bfr[2][4];
            const int ksa = ks * 2 + aHi;
            const int ksb = ks * 2 + bHi;
#pragma unroll
            for (int i = 0; i < 4; i++)
                ldsm4(afr[i], As + aR[i] * 128 + (((ksa ^ (aR[i] & 7))) << 4));
#pragma unroll
            for (int j2 = 0; j2 < 2; j2++)
                ldsm4(bfr[j2], Bs + bR[j2] * 128 + (((ksb ^ (bR[j2] & 7))) << 4));
#pragma unroll
            for (int i = 0; i < 4; i++)
#pragma unroll
                for (int j = 0; j < 4; j++)
                    mma_s8(acc[i][j], afr[i], &bfr[j >> 1][(j & 1) * 2]);
        }
        __syncthreads();
        if (it + 2 < KITERS) load_stage(it + 2);
        else cp_commit();
    }

    // Epilogue: out = acc * ws / sx[row]; layer0 adds relu^2. Exact ints in acc.
    const float ws = g_wscale[LAYER];
#pragma unroll
    for (int i = 0; i < 4; i++) {
        const int r0 = bm * GBM + wm * 64 + i * 16 + (lane >> 2);
        const float fa = ws / sx[r0];
        const float fb = ws / sx[r0 + 8];
#pragma unroll
        for (int j = 0; j < 4; j++) {
            const int c0 = bn * GBN + wn * 32 + j * 8 + (lane & 3) * 2;
            float e0 = (float)acc[i][j][0] * fa;
            float e1 = (float)acc[i][j][1] * fa;
            float e2 = (float)acc[i][j][2] * fb;
            float e3 = (float)acc[i][j][3] * fb;
            if (LAYER == 0) {
                e0 = fmaxf(e0, 0.f); e0 *= e0;
                e1 = fmaxf(e1, 0.f); e1 *= e1;
                e2 = fmaxf(e2, 0.f); e2 *= e2;
                e3 = fmaxf(e3, 0.f); e3 *= e3;
            }
            *(float2*)(C + (size_t)r0 * N + c0)       = make_float2(e0, e1);
            *(float2*)(C + (size_t)(r0 + 8) * N + c0) = make_float2(e2, e3);
        }
    }
}

// ---------------------------------------------------------------------------
// Launch
// ---------------------------------------------------------------------------
extern "C" void kernel_launch(void* const* d_in, const int* in_sizes, int n_in,
                              void* d_out, int out_size) {
    (void)in_sizes; (void)n_in; (void)out_size;
    const float* x  = (const float*)d_in[0];   // hidden_states [4,2048,2048]
    const float* wu = (const float*)d_in[1];   // w_up   [4096,2048]
    const float* wd = (const float*)d_in[2];   // w_down [2048,4096]
    float* out = (float*)d_out;                // fp32 out

    cudaFuncSetAttribute(gemm_imma_kernel<0>, cudaFuncAttributeMaxDynamicSharedMemorySize, SMEM_GEMM);
    cudaFuncSetAttribute(gemm_imma_kernel<1>, cudaFuncAttributeMaxDynamicSharedMemorySize, SMEM_GEMM);

    const int nup = I_DIM * H_DIM;
    const int ndn = H_DIM * I_DIM;

    absmean_partial_kernel<<<1024, 256>>>(wu, nup);
    absmean_final_kernel<<<1, 256>>>(nup, 0);
    quant_w_kernel<<<2048, 256>>>(wu, nup, 0);
    absmean_partial_kernel<<<1024, 256>>>(wd, ndn);
    absmean_final_kernel<<<1, 256>>>(ndn, 1);
    quant_w_kernel<<<2048, 256>>>(wd, ndn, 1);

    fwht_quant_kernel<H_DIM, 0><<<TOK, 256>>>(x);
    gemm_imma_kernel<0><<<dim3(I_DIM / GBN, TOK / GBM), 256, SMEM_GEMM>>>(nullptr);

    fwht_quant_kernel<I_DIM, 1><<<TOK, 256>>>(nullptr);
    gemm_imma_kernel<1><<<dim3(H_DIM / GBN, TOK / GBM), 256, SMEM_GEMM>>>(out);
}